// round 1
// baseline (speedup 1.0000x reference)
#include <cuda_runtime.h>
#include <math.h>

#define SEQ    4096
#define HIDDEN 2048
#define NHEAD  16
#define NKVH   8
#define HDIM   128

// ---------------- scratch (static device globals; no allocation) ----------
__device__ float g_q  [SEQ * NHEAD * HDIM];   // [s][h*128+d]
__device__ float g_k  [SEQ * NKVH  * HDIM];
__device__ float g_v  [SEQ * NKVH  * HDIM];
__device__ float g_ao [SEQ * NHEAD * HDIM];
__device__ float g_cos[SEQ * 64];
__device__ float g_sin[SEQ * 64];

// ---------------------------------------------------------------------------
// SGEMM: C[M,N] = A[M,K] * B[N,K]^T, all row-major. 128x128x16 tiles,
// 256 threads, 8x8 per thread, double-buffered smem, reg-prefetched LDG.
// ---------------------------------------------------------------------------
__global__ __launch_bounds__(256)
void sgemm_nt(const float* __restrict__ A, const float* __restrict__ B,
              float* __restrict__ C, int M, int N, int K)
{
    __shared__ float As[2][16][132];
    __shared__ float Bs[2][16][132];

    const int tid = threadIdx.x;
    const int bm = blockIdx.y * 128, bn = blockIdx.x * 128;
    const int ty = tid >> 4, tx = tid & 15;

    const float* Ag = A + (size_t)bm * K;
    const float* Bg = B + (size_t)bn * K;

    float acc[8][8];
#pragma unroll
    for (int i = 0; i < 8; i++)
#pragma unroll
        for (int j = 0; j < 8; j++) acc[i][j] = 0.f;

    const int r0 = tid >> 2;            // rows r0, r0+64
    const int c0 = (tid & 3) * 4;       // k-offset within tile

    float4 pa[2], pb[2];
#pragma unroll
    for (int i = 0; i < 2; i++) {
        pa[i] = *(const float4*)(Ag + (size_t)(r0 + 64 * i) * K + c0);
        pb[i] = *(const float4*)(Bg + (size_t)(r0 + 64 * i) * K + c0);
    }
#pragma unroll
    for (int i = 0; i < 2; i++) {
        int rr = r0 + 64 * i;
        As[0][c0 + 0][rr] = pa[i].x; As[0][c0 + 1][rr] = pa[i].y;
        As[0][c0 + 2][rr] = pa[i].z; As[0][c0 + 3][rr] = pa[i].w;
        Bs[0][c0 + 0][rr] = pb[i].x; Bs[0][c0 + 1][rr] = pb[i].y;
        Bs[0][c0 + 2][rr] = pb[i].z; Bs[0][c0 + 3][rr] = pb[i].w;
    }
    __syncthreads();

    int buf = 0;
    for (int k0 = 0; k0 < K; k0 += 16) {
        const bool more = (k0 + 16) < K;
        if (more) {
#pragma unroll
            for (int i = 0; i < 2; i++) {
                pa[i] = *(const float4*)(Ag + (size_t)(r0 + 64 * i) * K + k0 + 16 + c0);
                pb[i] = *(const float4*)(Bg + (size_t)(r0 + 64 * i) * K + k0 + 16 + c0);
            }
        }
#pragma unroll
        for (int kk = 0; kk < 16; kk++) {
            float a[8], b[8];
            *(float4*)&a[0] = *(const float4*)&As[buf][kk][ty * 8];
            *(float4*)&a[4] = *(const float4*)&As[buf][kk][ty * 8 + 4];
            *(float4*)&b[0] = *(const float4*)&Bs[buf][kk][tx * 8];
            *(float4*)&b[4] = *(const float4*)&Bs[buf][kk][tx * 8 + 4];
#pragma unroll
            for (int i = 0; i < 8; i++)
#pragma unroll
                for (int j = 0; j < 8; j++)
                    acc[i][j] = fmaf(a[i], b[j], acc[i][j]);
        }
        if (more) {
            int nb = buf ^ 1;
#pragma unroll
            for (int i = 0; i < 2; i++) {
                int rr = r0 + 64 * i;
                As[nb][c0 + 0][rr] = pa[i].x; As[nb][c0 + 1][rr] = pa[i].y;
                As[nb][c0 + 2][rr] = pa[i].z; As[nb][c0 + 3][rr] = pa[i].w;
                Bs[nb][c0 + 0][rr] = pb[i].x; Bs[nb][c0 + 1][rr] = pb[i].y;
                Bs[nb][c0 + 2][rr] = pb[i].z; Bs[nb][c0 + 3][rr] = pb[i].w;
            }
        }
        __syncthreads();
        buf ^= 1;
    }

    float* Cp = C + (size_t)(bm + ty * 8) * N + bn + tx * 8;
#pragma unroll
    for (int i = 0; i < 8; i++) {
#pragma unroll
        for (int j4 = 0; j4 < 2; j4++) {
            float4 v;
            v.x = acc[i][j4 * 4 + 0]; v.y = acc[i][j4 * 4 + 1];
            v.z = acc[i][j4 * 4 + 2]; v.w = acc[i][j4 * 4 + 3];
            *(float4*)(Cp + (size_t)i * N + j4 * 4) = v;
        }
    }
}

// ---------------------------------------------------------------------------
// RoPE cos/sin table. fp32 angle computed exactly like JAX (fp32 product of
// fp32 inv_freq), trig in double so --use_fast_math cannot wreck large-arg
// range reduction.
// ---------------------------------------------------------------------------
__global__ void rope_table_kernel()
{
    int idx = blockIdx.x * 256 + threadIdx.x;
    if (idx >= SEQ * 64) return;
    int s = idx >> 6, f = idx & 63;
    double invf = pow(1.0e6, -(double)f / 64.0);
    float ang = (float)s * (float)invf;
    g_cos[idx] = (float)cos((double)ang);
    g_sin[idx] = (float)sin((double)ang);
}

// ---------------------------------------------------------------------------
// Per-(s,head) RMSNorm over 128 dims + RoPE, in-place. One block per row.
// ---------------------------------------------------------------------------
__global__ __launch_bounds__(128)
void qk_norm_rope(float* __restrict__ X, const float* __restrict__ W, int nh)
{
    const int s = blockIdx.x, hh = blockIdx.y, d = threadIdx.x;
    float* row = X + ((size_t)s * nh + hh) * HDIM;
    float v = row[d];

    float ss = v * v;
#pragma unroll
    for (int o = 16; o > 0; o >>= 1) ss += __shfl_xor_sync(0xffffffffu, ss, o);
    __shared__ float wsum[4];
    __shared__ float sh[128];
    if ((d & 31) == 0) wsum[d >> 5] = ss;
    __syncthreads();
    float tot = wsum[0] + wsum[1] + wsum[2] + wsum[3];
    float r = rsqrtf(tot * (1.0f / 128.0f) + 1e-6f);
    v = v * r * W[d];

    sh[d] = v;
    __syncthreads();
    int f = d & 63;
    float c  = g_cos[s * 64 + f];
    float sn = g_sin[s * 64 + f];
    float o2 = sh[d ^ 64];
    row[d] = (d < 64) ? (v * c - o2 * sn) : (v * c + o2 * sn);
}

// ---------------------------------------------------------------------------
// Causal GQA flash attention, fp32. 64x64 tiles, 256 threads.
// Strided per-thread sub-tiles (index = t + 16*i) for conflict-free smem.
// ---------------------------------------------------------------------------
#define LDQ 132
#define LDP 68

__global__ __launch_bounds__(256)
void flash_attn(const float* __restrict__ Q, const float* __restrict__ K,
                const float* __restrict__ V, float* __restrict__ O)
{
    extern __shared__ float sm[];
    float* Qs = sm;                 // [64][132]
    float* Ks = sm + 64 * LDQ;      // [64][132]
    float* Vs = sm + 2 * 64 * LDQ;  // [64][132]
    float* Ps = sm + 3 * 64 * LDQ;  // [64][68]

    const int h   = blockIdx.y;
    const int qi  = (int)gridDim.x - 1 - (int)blockIdx.x;  // heavy blocks first
    const int kvh = h >> 1;                                  // GQA: 2 q-heads / kv-head
    const int tid = threadIdx.x;
    const int ty = tid >> 4, tx = tid & 15;

    const float* Qg = Q + (size_t)(qi * 64) * (NHEAD * HDIM) + h * HDIM;
    const float* Kg = K + (size_t)kvh * HDIM;
    const float* Vg = V + (size_t)kvh * HDIM;

    const float scale = 0.08838834764831845f;  // 1/sqrt(128)
#pragma unroll
    for (int i = 0; i < 8; i++) {
        int idx = tid + i * 256;
        int r = idx >> 5, c4 = (idx & 31) * 4;
        float4 v = *(const float4*)(Qg + (size_t)r * (NHEAD * HDIM) + c4);
        v.x *= scale; v.y *= scale; v.z *= scale; v.w *= scale;
        *(float4*)&Qs[r * LDQ + c4] = v;
    }

    float m[4], l[4], acc[4][8];
#pragma unroll
    for (int ii = 0; ii < 4; ii++) {
        m[ii] = -3.0e38f; l[ii] = 0.f;
#pragma unroll
        for (int jj = 0; jj < 8; jj++) acc[ii][jj] = 0.f;
    }

    const int ntiles = qi + 1;
    for (int j = 0; j < ntiles; j++) {
        // ---- load K/V tile (coalesced) ----
#pragma unroll
        for (int i = 0; i < 8; i++) {
            int idx = tid + i * 256;
            int r = idx >> 5, c4 = (idx & 31) * 4;
            size_t goff = (size_t)(j * 64 + r) * (NKVH * HDIM) + c4;
            *(float4*)&Ks[r * LDQ + c4] = *(const float4*)(Kg + goff);
            *(float4*)&Vs[r * LDQ + c4] = *(const float4*)(Vg + goff);
        }
        __syncthreads();

        // ---- S = Qs @ Ks^T (per-thread 4x4 strided tile) ----
        float sacc[4][4];
#pragma unroll
        for (int ii = 0; ii < 4; ii++)
#pragma unroll
            for (int jj = 0; jj < 4; jj++) sacc[ii][jj] = 0.f;

#pragma unroll 4
        for (int k4 = 0; k4 < 32; k4++) {
            float4 qa[4], kb[4];
#pragma unroll
            for (int ii = 0; ii < 4; ii++)
                qa[ii] = *(const float4*)&Qs[(ty + 16 * ii) * LDQ + k4 * 4];
#pragma unroll
            for (int jj = 0; jj < 4; jj++)
                kb[jj] = *(const float4*)&Ks[(tx + 16 * jj) * LDQ + k4 * 4];
#pragma unroll
            for (int ii = 0; ii < 4; ii++)
#pragma unroll
                for (int jj = 0; jj < 4; jj++) {
                    sacc[ii][jj] = fmaf(qa[ii].x, kb[jj].x, sacc[ii][jj]);
                    sacc[ii][jj] = fmaf(qa[ii].y, kb[jj].y, sacc[ii][jj]);
                    sacc[ii][jj] = fmaf(qa[ii].z, kb[jj].z, sacc[ii][jj]);
                    sacc[ii][jj] = fmaf(qa[ii].w, kb[jj].w, sacc[ii][jj]);
                }
        }

        // ---- online softmax ----
        const int row0 = qi * 64, col0 = j * 64;
#pragma unroll
        for (int ii = 0; ii < 4; ii++) {
            int rg = row0 + ty + 16 * ii;
            float mx = m[ii];
#pragma unroll
            for (int jj = 0; jj < 4; jj++) {
                int cg = col0 + tx + 16 * jj;
                if (cg > rg) sacc[ii][jj] = -1e30f;   // causal mask
                mx = fmaxf(mx, sacc[ii][jj]);
            }
            mx = fmaxf(mx, __shfl_xor_sync(0xffffffffu, mx, 1));
            mx = fmaxf(mx, __shfl_xor_sync(0xffffffffu, mx, 2));
            mx = fmaxf(mx, __shfl_xor_sync(0xffffffffu, mx, 4));
            mx = fmaxf(mx, __shfl_xor_sync(0xffffffffu, mx, 8));

            float alpha = __expf(m[ii] - mx);
            float rs = 0.f;
#pragma unroll
            for (int jj = 0; jj < 4; jj++) {
                float p = __expf(sacc[ii][jj] - mx);
                Ps[(ty + 16 * ii) * LDP + tx + 16 * jj] = p;
                rs += p;
            }
            rs += __shfl_xor_sync(0xffffffffu, rs, 1);
            rs += __shfl_xor_sync(0xffffffffu, rs, 2);
            rs += __shfl_xor_sync(0xffffffffu, rs, 4);
            rs += __shfl_xor_sync(0xffffffffu, rs, 8);

            l[ii] = l[ii] * alpha + rs;
            m[ii] = mx;
#pragma unroll
            for (int jj = 0; jj < 8; jj++) acc[ii][jj] *= alpha;
        }
        __syncthreads();

        // ---- acc += P @ V ----
#pragma unroll 4
        for (int k4 = 0; k4 < 16; k4++) {
            float pr[4][4];
#pragma unroll
            for (int ii = 0; ii < 4; ii++)
                *(float4*)pr[ii] = *(const float4*)&Ps[(ty + 16 * ii) * LDP + k4 * 4];
#pragma unroll
            for (int u = 0; u < 4; u++) {
                int kk = k4 * 4 + u;
#pragma unroll
                for (int jj = 0; jj < 8; jj++) {
                    float b = Vs[kk * LDQ + tx + 16 * jj];
#pragma unroll
                    for (int ii = 0; ii < 4; ii++)
                        acc[ii][jj] = fmaf(pr[ii][u], b, acc[ii][jj]);
                }
            }
        }
        __syncthreads();
    }

    // ---- normalize and write ----
#pragma unroll
    for (int ii = 0; ii < 4; ii++) {
        float inv = 1.f / l[ii];
        int rg = qi * 64 + ty + 16 * ii;
        float* op = O + (size_t)rg * (NHEAD * HDIM) + h * HDIM;
#pragma unroll
        for (int jj = 0; jj < 8; jj++)
            op[tx + 16 * jj] = acc[ii][jj] * inv;
    }
}

// ---------------------------------------------------------------------------
extern "C" void kernel_launch(void* const* d_in, const int* in_sizes, int n_in,
                              void* d_out, int out_size)
{
    const float* hs  = (const float*)d_in[0];
    // d_in[1] = attention_mask (pure causal; implemented analytically)
    const float* wq  = (const float*)d_in[2];
    const float* wk  = (const float*)d_in[3];
    const float* wv  = (const float*)d_in[4];
    const float* wo  = (const float*)d_in[5];
    const float* qnw = (const float*)d_in[6];
    const float* knw = (const float*)d_in[7];
    float* out = (float*)d_out;

    float *gq, *gk, *gv, *gao;
    cudaGetSymbolAddress((void**)&gq,  g_q);
    cudaGetSymbolAddress((void**)&gk,  g_k);
    cudaGetSymbolAddress((void**)&gv,  g_v);
    cudaGetSymbolAddress((void**)&gao, g_ao);

    const int flash_smem = (3 * 64 * LDQ + 64 * LDP) * (int)sizeof(float); // 118784
    cudaFuncSetAttribute(flash_attn, cudaFuncAttributeMaxDynamicSharedMemorySize,
                         flash_smem);

    // QKV projections
    sgemm_nt<<<dim3(16, 32), 256>>>(hs, wq, gq, SEQ, NHEAD * HDIM, HIDDEN);
    sgemm_nt<<<dim3(8, 32), 256>>>(hs, wk, gk, SEQ, NKVH * HDIM, HIDDEN);
    sgemm_nt<<<dim3(8, 32), 256>>>(hs, wv, gv, SEQ, NKVH * HDIM, HIDDEN);

    // RoPE tables + per-head RMSNorm + RoPE
    rope_table_kernel<<<SEQ * 64 / 256, 256>>>();
    qk_norm_rope<<<dim3(SEQ, NHEAD), 128>>>(gq, qnw, NHEAD);
    qk_norm_rope<<<dim3(SEQ, NKVH), 128>>>(gk, knw, NKVH);

    // causal GQA attention
    flash_attn<<<dim3(SEQ / 64, NHEAD), 256, flash_smem>>>(gq, gk, gv, gao);

    // O projection -> final output
    sgemm_nt<<<dim3(16, 32), 256>>>(gao, wo, out, SEQ, NHEAD * HDIM, HIDDEN);
}